// round 9
// baseline (speedup 1.0000x reference)
#include <cuda_runtime.h>
#include <math.h>

// Problem constants
#define B   256
#define L   512
#define I   32
#define H   16
#define G   64            // 4*H gates
#define NT  511           // number of increments
#define SIGD 4368         // H + H^2 + H^3
#define O   10

// Scratch (device globals; no allocation allowed)
static __device__ float g_xw[B * L * G];        // 33.5 MB : input projection + biases
static __device__ float g_d [B * NT * H];       // 8.4 MB  : h increments d_t = h_{t+1}-h_t

// ---------------------------------------------------------------------------
// Activations via hardware MUFU.TANH (lat 16).
// sigmoid(x) = 0.5*tanh(x/2) + 0.5  (exact identity; only tanh is approx)
// ---------------------------------------------------------------------------
__device__ __forceinline__ float tanh_hw(float x) {
    float y; asm("tanh.approx.f32 %0, %1;" : "=f"(y) : "f"(x)); return y;
}
__device__ __forceinline__ float sigmoid_hw(float x) {
    return fmaf(tanh_hw(0.5f * x), 0.5f, 0.5f);
}

// ---------------------------------------------------------------------------
// Packed fp32x2 helpers (Blackwell FFMA2 via PTX) — sig kernel only
// ---------------------------------------------------------------------------
typedef unsigned long long u64t;
__device__ __forceinline__ u64t pack2_(float lo, float hi) {
    u64t r; asm("mov.b64 %0, {%1, %2};" : "=l"(r) : "f"(lo), "f"(hi)); return r;
}
__device__ __forceinline__ void unpack2_(u64t v, float& lo, float& hi) {
    asm("mov.b64 {%0, %1}, %2;" : "=f"(lo), "=f"(hi) : "l"(v));
}
__device__ __forceinline__ u64t ffma2_(u64t a, u64t b, u64t c) {
    u64t d; asm("fma.rn.f32x2 %0, %1, %2, %3;" : "=l"(d) : "l"(a), "l"(b), "l"(c));
    return d;
}

// ---------------------------------------------------------------------------
// K1: xw[bt][g] = b_ih[g] + b_hh[g] + sum_i X[bt][i] * W_ih[g][i]
// EXACT round-2 version (measured 27.8us across three rounds) — FROZEN.
// ---------------------------------------------------------------------------
__global__ void __launch_bounds__(256) xw_kernel(const float* __restrict__ X,
                                                 const float* __restrict__ Wih,
                                                 const float* __restrict__ bih,
                                                 const float* __restrict__ bhh) {
    __shared__ float Xs[64 * 33];
    __shared__ float Ws[32 * 65];
    __shared__ float bs[64];

    int tid = threadIdx.x;
    int bt0 = blockIdx.x * 64;
    const float* Xg = X + (size_t)bt0 * I;

    for (int i = tid; i < 64 * I; i += 256) {
        int r = i >> 5, k = i & 31;
        Xs[r * 33 + k] = Xg[i];
        Ws[k * 65 + r] = Wih[i];
    }
    if (tid < 64) bs[tid] = bih[tid] + bhh[tid];
    __syncthreads();

    int tg = tid & 15;
    int tb = tid >> 4;
    float acc[4][4];
#pragma unroll
    for (int bi = 0; bi < 4; bi++)
#pragma unroll
        for (int gi = 0; gi < 4; gi++)
            acc[bi][gi] = bs[tg * 4 + gi];

#pragma unroll 8
    for (int k = 0; k < I; k++) {
        float xv[4], wv[4];
#pragma unroll
        for (int bi = 0; bi < 4; bi++) xv[bi] = Xs[(tb * 4 + bi) * 33 + k];
#pragma unroll
        for (int gi = 0; gi < 4; gi++) wv[gi] = Ws[k * 65 + tg * 4 + gi];
#pragma unroll
        for (int bi = 0; bi < 4; bi++)
#pragma unroll
            for (int gi = 0; gi < 4; gi++)
                acc[bi][gi] = fmaf(xv[bi], wv[gi], acc[bi][gi]);
    }

#pragma unroll
    for (int bi = 0; bi < 4; bi++) {
        int bt = bt0 + tb * 4 + bi;
        float4 v = make_float4(acc[bi][0], acc[bi][1], acc[bi][2], acc[bi][3]);
        *reinterpret_cast<float4*>(g_xw + (size_t)bt * G + tg * 4) = v;
    }
}

// ---------------------------------------------------------------------------
// K2: LSTM recurrence. R5 per-batch structure, but each warp now runs TWO
// independent batch chains interleaved in time (A and B). Weights are shared
// registers (identical across batches — no extra weight pressure). The two
// ~180-cycle dependency chains overlap, hiding each other's latency.
// One syncwarp covers both batches' h broadcasts.
// ---------------------------------------------------------------------------
__global__ void __launch_bounds__(128) lstm_kernel(const float* __restrict__ Whh) {
    __shared__ __align__(16) float hsm[4][2][2][16];   // [warp][A/B][buf][j]
    int lane = threadIdx.x & 31;
    int warp = threadIdx.x >> 5;
    int b0 = blockIdx.x * 8 + warp * 2;                // batches b0 (A), b0+1 (B)

    float w0[H], w1[H];
#pragma unroll
    for (int j = 0; j < H; j++) {
        w0[j] = __ldg(Whh + lane * H + j);
        w1[j] = __ldg(Whh + (lane + 32) * H + j);
    }

    float hA[H], hB[H];
#pragma unroll
    for (int j = 0; j < H; j++) { hA[j] = 0.f; hB[j] = 0.f; }
    float cA = 0.f, cB = 0.f, hpA = 0.f, hpB = 0.f;

    const float* xpA = g_xw + (size_t)b0 * (L * G) + lane;
    const float* xpB = xpA + (size_t)(L * G);
    float* dpA = g_d + (size_t)b0 * (NT * H);
    float* dpB = dpA + (size_t)(NT * H);

    // 2-deep prefetch per batch (4 outstanding loads total ≈ same coverage)
    float bxA0[2], bxA1[2], bxB0[2], bxB1[2];
#pragma unroll
    for (int k = 0; k < 2; k++) {
        bxA0[k] = xpA[k * G]; bxA1[k] = xpA[k * G + 32];
        bxB0[k] = xpB[k * G]; bxB1[k] = xpB[k * G + 32];
    }

#pragma unroll 2
    for (int t = 0; t < L; t++) {
        int slot = t & 1;
        float a0A = bxA0[slot], a1A = bxA1[slot];
        float a0B = bxB0[slot], a1B = bxB1[slot];
        if (t + 2 < L) {
            bxA0[slot] = xpA[(t + 2) * G]; bxA1[slot] = xpA[(t + 2) * G + 32];
            bxB0[slot] = xpB[(t + 2) * G]; bxB1[slot] = xpB[(t + 2) * G + 32];
        }

        float q0A = 0.f, q1A = 0.f, q0B = 0.f, q1B = 0.f;
#pragma unroll
        for (int j = 0; j < 8; j++) {
            a0A = fmaf(hA[j],     w0[j],     a0A);
            q0A = fmaf(hA[j + 8], w0[j + 8], q0A);
            a1A = fmaf(hA[j],     w1[j],     a1A);
            q1A = fmaf(hA[j + 8], w1[j + 8], q1A);
            a0B = fmaf(hB[j],     w0[j],     a0B);
            q0B = fmaf(hB[j + 8], w0[j + 8], q0B);
            a1B = fmaf(hB[j],     w1[j],     a1B);
            q1B = fmaf(hB[j + 8], w1[j + 8], q1B);
        }
        a0A += q0A; a1A += q1A;
        a0B += q0B; a1B += q1B;

        float fgA = __shfl_down_sync(0xffffffffu, a0A, 16);
        float ogA = __shfl_down_sync(0xffffffffu, a1A, 16);
        float fgB = __shfl_down_sync(0xffffffffu, a0B, 16);
        float ogB = __shfl_down_sync(0xffffffffu, a1B, 16);

        float siA = sigmoid_hw(a0A);
        float sfA = sigmoid_hw(fgA);
        float soA = sigmoid_hw(ogA);
        float tgA = tanh_hw(a1A);
        float siB = sigmoid_hw(a0B);
        float sfB = sigmoid_hw(fgB);
        float soB = sigmoid_hw(ogB);
        float tgB = tanh_hw(a1B);

        cA = fmaf(sfA, cA, siA * tgA);
        cB = fmaf(sfB, cB, siB * tgB);
        float hnA = soA * tanh_hw(cA);
        float hnB = soB * tanh_hw(cB);

        int buf = t & 1;
        if (lane < H) {
            hsm[warp][0][buf][lane] = hnA;
            hsm[warp][1][buf][lane] = hnB;
            if (t) {
                dpA[(t - 1) * H + lane] = hnA - hpA;
                dpB[(t - 1) * H + lane] = hnB - hpB;
            }
            hpA = hnA; hpB = hnB;
        }
        __syncwarp();
#pragma unroll
        for (int j = 0; j < H; j += 4) {
            float4 vA = *reinterpret_cast<const float4*>(&hsm[warp][0][buf][j]);
            float4 vB = *reinterpret_cast<const float4*>(&hsm[warp][1][buf][j]);
            hA[j] = vA.x; hA[j + 1] = vA.y; hA[j + 2] = vA.z; hA[j + 3] = vA.w;
            hB[j] = vB.x; hB[j + 1] = vB.y; hB[j + 2] = vB.z; hB[j + 3] = vB.w;
        }
    }
}

// ---------------------------------------------------------------------------
// K3: depth-3 signature scan + fused FC epilogue. One 256-thread CTA / batch.
// Thread tid = (a,b): S2[a][b] scalar, S3[a][b][0..15] as 8 packed f32x2.
// Increment rows loaded directly as ulonglong2 (halves are FFMA2 operands).
// ---------------------------------------------------------------------------
__global__ void __launch_bounds__(256) sig_kernel(const float* __restrict__ fcw,
                                                  const float* __restrict__ fcb,
                                                  float* __restrict__ out) {
    __shared__ __align__(16) float ds[NT * H];   // 32704 B
    __shared__ float red[8][O];
    int bidx = blockIdx.x;
    int tid = threadIdx.x;

    {
        const float4* s4 = reinterpret_cast<const float4*>(g_d + (size_t)bidx * (NT * H));
        float4* t4 = reinterpret_cast<float4*>(ds);
        for (int i = tid; i < (NT * H) / 4; i += 256) t4[i] = s4[i];
    }
    __syncthreads();

    int a  = tid >> 4;
    int bb = tid & 15;

    float S1h = 0.f, S2 = 0.f;       // S1h = S1/2 (exact scaling)
    u64t S3p[8];
#pragma unroll
    for (int j = 0; j < 8; j++) S3p[j] = 0ull;

#pragma unroll 2
    for (int t = 0; t < NT; t++) {
        const float* dr = ds + t * H;
        ulonglong2 p0 = *reinterpret_cast<const ulonglong2*>(dr);
        ulonglong2 p1 = *reinterpret_cast<const ulonglong2*>(dr + 4);
        ulonglong2 p2 = *reinterpret_cast<const ulonglong2*>(dr + 8);
        ulonglong2 p3 = *reinterpret_cast<const ulonglong2*>(dr + 12);
        float da = dr[a];
        float db = dr[bb];

        float m1   = da * db;
        float db2  = db + db;
        float coef = fmaf(S1h, db, fmaf(m1, (1.f / 6.f), S2));
        u64t cp = pack2_(coef, coef);

        S3p[0] = ffma2_(cp, p0.x, S3p[0]);
        S3p[1] = ffma2_(cp, p0.y, S3p[1]);
        S3p[2] = ffma2_(cp, p1.x, S3p[2]);
        S3p[3] = ffma2_(cp, p1.y, S3p[3]);
        S3p[4] = ffma2_(cp, p2.x, S3p[4]);
        S3p[5] = ffma2_(cp, p2.y, S3p[5]);
        S3p[6] = ffma2_(cp, p3.x, S3p[6]);
        S3p[7] = ffma2_(cp, p3.y, S3p[7]);

        S2  = fmaf(S1h, db2, fmaf(0.5f, m1, S2));
        S1h = fmaf(0.5f, da, S1h);
    }

    // ---- fused FC: out[b][o] = sig . fc_w[o] + fc_b[o] ----
    float S3[16];
#pragma unroll
    for (int j = 0; j < 8; j++) unpack2_(S3p[j], S3[2 * j], S3[2 * j + 1]);
    float S1 = S1h + S1h;

    float part[O];
#pragma unroll
    for (int o = 0; o < O; o++) {
        const float* wr = fcw + (size_t)o * SIGD;
        float acc = S2 * __ldg(wr + H + tid);              // level-2 term
        if (bb == 0) acc = fmaf(S1, __ldg(wr + a), acc);   // level-1 term
        const float4* w4 = reinterpret_cast<const float4*>(wr + H + H * H + tid * 16);
#pragma unroll
        for (int j = 0; j < 4; j++) {
            float4 w = __ldg(w4 + j);
            acc = fmaf(S3[4 * j + 0], w.x, acc);
            acc = fmaf(S3[4 * j + 1], w.y, acc);
            acc = fmaf(S3[4 * j + 2], w.z, acc);
            acc = fmaf(S3[4 * j + 3], w.w, acc);
        }
        part[o] = acc;
    }

    int lane = tid & 31, warp = tid >> 5;
#pragma unroll
    for (int off = 16; off > 0; off >>= 1)
#pragma unroll
        for (int o = 0; o < O; o++)
            part[o] += __shfl_down_sync(0xffffffffu, part[o], off);
    if (lane == 0)
#pragma unroll
        for (int o = 0; o < O; o++) red[warp][o] = part[o];
    __syncthreads();

    if (tid < O) {
        float v = fcb[tid];
#pragma unroll
        for (int w = 0; w < 8; w++) v += red[w][tid];
        out[bidx * O + tid] = v;
    }
}

// ---------------------------------------------------------------------------
extern "C" void kernel_launch(void* const* d_in, const int* in_sizes, int n_in,
                              void* d_out, int out_size) {
    const float* X   = (const float*)d_in[0];
    const float* Wih = (const float*)d_in[1];
    const float* Whh = (const float*)d_in[2];
    const float* bih = (const float*)d_in[3];
    const float* bhh = (const float*)d_in[4];
    const float* fcw = (const float*)d_in[5];
    const float* fcb = (const float*)d_in[6];
    float* out = (float*)d_out;

    xw_kernel<<<(B * L) / 64, 256>>>(X, Wih, bih, bhh);
    lstm_kernel<<<B / 8, 128>>>(Whh);
    sig_kernel<<<B, 256>>>(fcw, fcb, out);
}

// round 10
// speedup vs baseline: 1.6406x; 1.6406x over previous
#include <cuda_runtime.h>
#include <math.h>

// Problem constants
#define B   256
#define L   512
#define I   32
#define H   16
#define G   64            // 4*H gates
#define NT  511           // number of increments
#define SIGD 4368         // H + H^2 + H^3
#define O   10

// Scratch (device global; no allocation allowed)
static __device__ float g_xw[B * L * G];        // 33.5 MB : per-batch input projection

// ---------------------------------------------------------------------------
// Activations via hardware MUFU.TANH (lat 16).
// sigmoid(x) = 0.5*tanh(x/2) + 0.5  (exact identity; only tanh is approx)
// ---------------------------------------------------------------------------
__device__ __forceinline__ float tanh_hw(float x) {
    float y; asm("tanh.approx.f32 %0, %1;" : "=f"(y) : "f"(x)); return y;
}
__device__ __forceinline__ float sigmoid_hw(float x) {
    return fmaf(tanh_hw(0.5f * x), 0.5f, 0.5f);
}

// ---------------------------------------------------------------------------
// Packed fp32x2 helpers (Blackwell FFMA2 via PTX) — sig phase only
// ---------------------------------------------------------------------------
typedef unsigned long long u64t;
__device__ __forceinline__ u64t pack2_(float lo, float hi) {
    u64t r; asm("mov.b64 %0, {%1, %2};" : "=l"(r) : "f"(lo), "f"(hi)); return r;
}
__device__ __forceinline__ void unpack2_(u64t v, float& lo, float& hi) {
    asm("mov.b64 {%0, %1}, %2;" : "=f"(lo), "=f"(hi) : "l"(v));
}
__device__ __forceinline__ u64t ffma2_(u64t a, u64t b, u64t c) {
    u64t d; asm("fma.rn.f32x2 %0, %1, %2, %3;" : "=l"(d) : "l"(a), "l"(b), "l"(c));
    return d;
}

// ---------------------------------------------------------------------------
// FUSED kernel: one block (256 thr) per batch element.
//   Phase A: input projection xw for this batch (frozen xw inner structure,
//            8 chunks of 64 timestep-rows) -> g_xw slice (L2-hot).
//   Phase B: LSTM recurrence on warp 0 (EXACT frozen R5 structure), writing
//            increments d_t straight into shared ds[] (no global roundtrip).
//   Phase C: depth-3 signature scan + fused FC (frozen structure) from ds.
// Different blocks overlap their phases across the chip.
// ---------------------------------------------------------------------------
__global__ void __launch_bounds__(256) fused_kernel(const float* __restrict__ X,
                                                    const float* __restrict__ Wih,
                                                    const float* __restrict__ Whh,
                                                    const float* __restrict__ bih,
                                                    const float* __restrict__ bhh,
                                                    const float* __restrict__ fcw,
                                                    const float* __restrict__ fcb,
                                                    float* __restrict__ out) {
    __shared__ __align__(16) float ds[NT * H];   // 32704 B; front 2112 floats alias Xs in phase A
    __shared__ float Ws[32 * 65];                // transposed W_ih [k][g]
    __shared__ float bs[64];
    __shared__ __align__(16) float hsm[2][16];
    __shared__ float red[8][O];

    int tid   = threadIdx.x;
    int batch = blockIdx.x;
    int lane  = tid & 31;
    int warp  = tid >> 5;

    float* xwb = g_xw + (size_t)batch * (L * G);

    // ================= Phase A: xw =================
    {
        float* Xs = ds;                           // alias: 64*33 = 2112 floats
        for (int i = tid; i < 2048; i += 256) {   // W_ih transpose (once)
            int g = i >> 5, k = i & 31;
            Ws[k * 65 + g] = Wih[i];
        }
        if (tid < 64) bs[tid] = bih[tid] + bhh[tid];

        int tg = tid & 15;
        int tb = tid >> 4;

        for (int c = 0; c < 8; c++) {
            const float* Xg = X + ((size_t)batch * L + c * 64) * I;
            __syncthreads();                      // protect Xs from prev chunk readers
            for (int i = tid; i < 2048; i += 256) {
                int r = i >> 5, k = i & 31;
                Xs[r * 33 + k] = Xg[i];
            }
            __syncthreads();

            float acc[4][4];
#pragma unroll
            for (int bi = 0; bi < 4; bi++)
#pragma unroll
                for (int gi = 0; gi < 4; gi++)
                    acc[bi][gi] = bs[tg * 4 + gi];

#pragma unroll 8
            for (int k = 0; k < I; k++) {
                float xv[4], wv[4];
#pragma unroll
                for (int bi = 0; bi < 4; bi++) xv[bi] = Xs[(tb * 4 + bi) * 33 + k];
#pragma unroll
                for (int gi = 0; gi < 4; gi++) wv[gi] = Ws[k * 65 + tg * 4 + gi];
#pragma unroll
                for (int bi = 0; bi < 4; bi++)
#pragma unroll
                    for (int gi = 0; gi < 4; gi++)
                        acc[bi][gi] = fmaf(xv[bi], wv[gi], acc[bi][gi]);
            }

#pragma unroll
            for (int bi = 0; bi < 4; bi++) {
                int row = c * 64 + tb * 4 + bi;
                float4 v = make_float4(acc[bi][0], acc[bi][1], acc[bi][2], acc[bi][3]);
                *reinterpret_cast<float4*>(xwb + (size_t)row * G + tg * 4) = v;
            }
        }
        __syncthreads();   // xw slice complete & visible block-wide (ds free)
    }

    // ================= Phase B: LSTM (warp 0 only; frozen R5 structure) ====
    if (warp == 0) {
        float w0[H], w1[H];
#pragma unroll
        for (int j = 0; j < H; j++) {
            w0[j] = __ldg(Whh + lane * H + j);
            w1[j] = __ldg(Whh + (lane + 32) * H + j);
        }
        float h[H];
#pragma unroll
        for (int j = 0; j < H; j++) h[j] = 0.f;
        float c = 0.f, hprev = 0.f;

        const float* xp = xwb + lane;

        float bx0[4], bx1[4];
#pragma unroll
        for (int k = 0; k < 4; k++) { bx0[k] = xp[k * G]; bx1[k] = xp[k * G + 32]; }

#pragma unroll 4
        for (int t = 0; t < L; t++) {
            int slot = t & 3;
            float a0 = bx0[slot], a1 = bx1[slot];
            if (t + 4 < L) { bx0[slot] = xp[(t + 4) * G]; bx1[slot] = xp[(t + 4) * G + 32]; }

            float q0 = 0.f, q1 = 0.f;
#pragma unroll
            for (int j = 0; j < 8; j++) {
                a0 = fmaf(h[j],     w0[j],     a0);
                q0 = fmaf(h[j + 8], w0[j + 8], q0);
                a1 = fmaf(h[j],     w1[j],     a1);
                q1 = fmaf(h[j + 8], w1[j + 8], q1);
            }
            a0 += q0; a1 += q1;

            float fg = __shfl_down_sync(0xffffffffu, a0, 16);  // lanes<16: f preact
            float og = __shfl_down_sync(0xffffffffu, a1, 16);  // lanes<16: o preact

            float si = sigmoid_hw(a0);
            float sf = sigmoid_hw(fg);
            float so = sigmoid_hw(og);
            float tg = tanh_hw(a1);
            c = fmaf(sf, c, si * tg);
            float hn = so * tanh_hw(c);

            int buf = t & 1;
            if (lane < H) {
                hsm[buf][lane] = hn;
                if (t) ds[(t - 1) * H + lane] = hn - hprev;   // increment to SHARED
                hprev = hn;
            }
            __syncwarp();
#pragma unroll
            for (int j = 0; j < H; j += 4) {
                float4 v = *reinterpret_cast<const float4*>(&hsm[buf][j]);
                h[j] = v.x; h[j + 1] = v.y; h[j + 2] = v.z; h[j + 3] = v.w;
            }
        }
    }
    __syncthreads();   // ds complete for all 256 threads

    // ================= Phase C: signature scan + FC (frozen structure) =====
    {
        int a  = tid >> 4;
        int bb = tid & 15;

        float S1h = 0.f, S2 = 0.f;       // S1h = S1/2 (exact scaling)
        u64t S3p[8];
#pragma unroll
        for (int j = 0; j < 8; j++) S3p[j] = 0ull;

#pragma unroll 2
        for (int t = 0; t < NT; t++) {
            const float* dr = ds + t * H;
            ulonglong2 p0 = *reinterpret_cast<const ulonglong2*>(dr);
            ulonglong2 p1 = *reinterpret_cast<const ulonglong2*>(dr + 4);
            ulonglong2 p2 = *reinterpret_cast<const ulonglong2*>(dr + 8);
            ulonglong2 p3 = *reinterpret_cast<const ulonglong2*>(dr + 12);
            float da = dr[a];
            float db = dr[bb];

            float m1   = da * db;
            float db2  = db + db;
            float coef = fmaf(S1h, db, fmaf(m1, (1.f / 6.f), S2));
            u64t cp = pack2_(coef, coef);

            S3p[0] = ffma2_(cp, p0.x, S3p[0]);
            S3p[1] = ffma2_(cp, p0.y, S3p[1]);
            S3p[2] = ffma2_(cp, p1.x, S3p[2]);
            S3p[3] = ffma2_(cp, p1.y, S3p[3]);
            S3p[4] = ffma2_(cp, p2.x, S3p[4]);
            S3p[5] = ffma2_(cp, p2.y, S3p[5]);
            S3p[6] = ffma2_(cp, p3.x, S3p[6]);
            S3p[7] = ffma2_(cp, p3.y, S3p[7]);

            S2  = fmaf(S1h, db2, fmaf(0.5f, m1, S2));
            S1h = fmaf(0.5f, da, S1h);
        }

        float S3[16];
#pragma unroll
        for (int j = 0; j < 8; j++) unpack2_(S3p[j], S3[2 * j], S3[2 * j + 1]);
        float S1 = S1h + S1h;

        float part[O];
#pragma unroll
        for (int o = 0; o < O; o++) {
            const float* wr = fcw + (size_t)o * SIGD;
            float acc = S2 * __ldg(wr + H + tid);              // level-2 term
            if (bb == 0) acc = fmaf(S1, __ldg(wr + a), acc);   // level-1 term
            const float4* w4 = reinterpret_cast<const float4*>(wr + H + H * H + tid * 16);
#pragma unroll
            for (int j = 0; j < 4; j++) {
                float4 w = __ldg(w4 + j);
                acc = fmaf(S3[4 * j + 0], w.x, acc);
                acc = fmaf(S3[4 * j + 1], w.y, acc);
                acc = fmaf(S3[4 * j + 2], w.z, acc);
                acc = fmaf(S3[4 * j + 3], w.w, acc);
            }
            part[o] = acc;
        }

#pragma unroll
        for (int off = 16; off > 0; off >>= 1)
#pragma unroll
            for (int o = 0; o < O; o++)
                part[o] += __shfl_down_sync(0xffffffffu, part[o], off);
        if (lane == 0)
#pragma unroll
            for (int o = 0; o < O; o++) red[warp][o] = part[o];
        __syncthreads();

        if (tid < O) {
            float v = fcb[tid];
#pragma unroll
            for (int w = 0; w < 8; w++) v += red[w][tid];
            out[batch * O + tid] = v;
        }
    }
}

// ---------------------------------------------------------------------------
extern "C" void kernel_launch(void* const* d_in, const int* in_sizes, int n_in,
                              void* d_out, int out_size) {
    const float* X   = (const float*)d_in[0];
    const float* Wih = (const float*)d_in[1];
    const float* Whh = (const float*)d_in[2];
    const float* bih = (const float*)d_in[3];
    const float* bhh = (const float*)d_in[4];
    const float* fcw = (const float*)d_in[5];
    const float* fcb = (const float*)d_in[6];
    float* out = (float*)d_out;

    fused_kernel<<<B, 256>>>(X, Wih, Whh, bih, bhh, fcw, fcb, out);
}